// round 13
// baseline (speedup 1.0000x reference)
#include <cuda_runtime.h>
#include <cuda_fp16.h>
#include <cstdint>

#define N_SEQ   2048
#define D_MODEL 1024
#define ATTN_SCALE 0.125f

// ---------------- scratch (fp16 operands, fp32 accumulation everywhere) -------
__device__ __half g_xh [N_SEQ * D_MODEL];
__device__ __half g_Wqh[D_MODEL * D_MODEL];
__device__ __half g_Wkh[D_MODEL * D_MODEL];
__device__ __half g_Wvh[D_MODEL * D_MODEL];
__device__ __half g_Woh[D_MODEL * D_MODEL];
__device__ __half g_Qh [N_SEQ * D_MODEL];
__device__ __half g_Kh [N_SEQ * D_MODEL];
__device__ __half g_Vh [N_SEQ * D_MODEL];
__device__ __half g_Vth[D_MODEL * N_SEQ];     // transposed V, [d][token]
__device__ __half g_AOh[N_SEQ * D_MODEL];

// ---------------- helpers ------------------------------------------------------
__device__ __forceinline__ void mma_f16(float c[4], const uint32_t a[4], const uint32_t b[2]) {
    asm volatile(
        "mma.sync.aligned.m16n8k16.row.col.f32.f16.f16.f32 "
        "{%0,%1,%2,%3}, {%4,%5,%6,%7}, {%8,%9}, {%0,%1,%2,%3};\n"
        : "+f"(c[0]), "+f"(c[1]), "+f"(c[2]), "+f"(c[3])
        : "r"(a[0]), "r"(a[1]), "r"(a[2]), "r"(a[3]), "r"(b[0]), "r"(b[1]));
}
__device__ __forceinline__ void ldsm4(uint32_t r[4], uint32_t addr) {
    asm volatile("ldmatrix.sync.aligned.m8n8.x4.shared.b16 {%0,%1,%2,%3}, [%4];"
                 : "=r"(r[0]), "=r"(r[1]), "=r"(r[2]), "=r"(r[3]) : "r"(addr));
}
#define CP16(dst, src) asm volatile("cp.async.cg.shared.global [%0], [%1], 16;" :: "r"(dst), "l"(src))
#define CPC            asm volatile("cp.async.commit_group;")
#define CPW(n)         asm volatile("cp.async.wait_group %0;" :: "n"(n))

// swizzled byte address: 128B rows, 8 x 16B chunks, chunk ^= (row & 7)
__device__ __forceinline__ uint32_t swad(uint32_t base, int row, int chunk) {
    return base + row * 128 + (((chunk) ^ (row & 7)) << 4);
}
__device__ __forceinline__ uint32_t packh2(float a, float b) {
    __half2 h = __floats2half2_rn(a, b);
    return *(uint32_t*)&h;
}

// ---------------- prep: f32 -> fp16 --------------------------------------------
__global__ __launch_bounds__(256) void prep_kernel(
    const float4* __restrict__ x,
    const float4* __restrict__ Wq, const float4* __restrict__ Wk,
    const float4* __restrict__ Wv, const float4* __restrict__ Wo) {
    const float4* src; __half2* dst; int n4;
    switch (blockIdx.y) {
        case 0:  src = x;  dst = (__half2*)g_xh;  n4 = 524288; break;
        case 1:  src = Wq; dst = (__half2*)g_Wqh; n4 = 262144; break;
        case 2:  src = Wk; dst = (__half2*)g_Wkh; n4 = 262144; break;
        case 3:  src = Wv; dst = (__half2*)g_Wvh; n4 = 262144; break;
        default: src = Wo; dst = (__half2*)g_Woh; n4 = 262144; break;
    }
    int i = blockIdx.x * 256 + threadIdx.x;
    if (i < n4) {
        float4 v = src[i];
        dst[2 * i]     = __floats2half2_rn(v.x, v.y);
        dst[2 * i + 1] = __floats2half2_rn(v.z, v.w);
    }
}

// ---------------- V transpose (half) --------------------------------------------
__global__ __launch_bounds__(256) void transposeV_kernel() {
    __shared__ __half t[32][33];
    const int tx = threadIdx.x & 31, ty = threadIdx.x >> 5;
    const int bx = blockIdx.x, by = blockIdx.y;
#pragma unroll
    for (int j = 0; j < 4; j++)
        t[ty + j * 8][tx] = g_Vh[(size_t)(by * 32 + ty + j * 8) * D_MODEL + bx * 32 + tx];
    __syncthreads();
#pragma unroll
    for (int j = 0; j < 4; j++)
        g_Vth[(size_t)(bx * 32 + ty + j * 8) * N_SEQ + by * 32 + tx] = t[tx][ty + j * 8];
}

// ---------------- GEMM fp16 (R8, proven): C = A @ W^T + bias --------------------
#define G_A(s)  ((s) * 16384)
#define G_B(s)  (32768 + (s) * 16384)
#define GEMM_SMEM 65536

template <bool HALF_OUT>
__device__ __forceinline__ void gemm_body(const __half* __restrict__ A, const __half* __restrict__ W,
                                          const float* __restrict__ bias, void* __restrict__ Cv) {
    extern __shared__ __align__(128) char smc[];
    const uint32_t sb = (uint32_t)__cvta_generic_to_shared(smc);
    const int tid = threadIdx.x, warp = tid >> 5, lane = tid & 31;
    const int grp = lane >> 2, four = lane & 3;
    const int wm = warp >> 2, wn = warp & 3;
    const int m0 = blockIdx.x * 128, n0 = blockIdx.y * 128;

    float acc[4][4][4];
#pragma unroll
    for (int mi = 0; mi < 4; mi++)
#pragma unroll
        for (int ni = 0; ni < 4; ni++)
#pragma unroll
            for (int j = 0; j < 4; j++) acc[mi][ni][j] = 0.f;

    const int lr = tid >> 3, lj = tid & 7;

    const int arow = wm * 64 + (lane & 15);
    const int acho = lane >> 4;
    const int brow = wn * 32 + ((lane >> 4) << 3) + (lane & 7);
    const int bcho = (lane >> 3) & 1;

#pragma unroll 1
    for (int kt = -1; kt < 16; kt++) {
        if (kt < 15) {
            const int s = (kt + 1) & 1, k0 = (kt + 1) * 64;
#pragma unroll
            for (int i = 0; i < 4; i++) {
                int r = lr + i * 32;
                CP16(swad(sb + G_A(s), r, lj), A + (size_t)(m0 + r) * D_MODEL + k0 + lj * 8);
                CP16(swad(sb + G_B(s), r, lj), W + (size_t)(n0 + r) * D_MODEL + k0 + lj * 8);
            }
            CPC;
        }
        if (kt < 0) continue;
        if (kt < 15) { CPW(1); } else { CPW(0); }
        __syncthreads();

        const int s = kt & 1;
        const uint32_t ab = sb + G_A(s), bbs = sb + G_B(s);
#pragma unroll
        for (int g = 0; g < 4; g++) {
            uint32_t a[4][4], bb[2][4];
#pragma unroll
            for (int mi = 0; mi < 4; mi++)
                ldsm4(a[mi], swad(ab, arow + mi * 16, g * 2 + acho));
#pragma unroll
            for (int p = 0; p < 2; p++)
                ldsm4(bb[p], swad(bbs, brow + p * 16, g * 2 + bcho));
#pragma unroll
            for (int mi = 0; mi < 4; mi++)
#pragma unroll
                for (int ni = 0; ni < 4; ni++)
                    mma_f16(acc[mi][ni], a[mi], &bb[ni >> 1][(ni & 1) << 1]);
        }
        __syncthreads();
    }

#pragma unroll
    for (int mi = 0; mi < 4; mi++) {
        int r = m0 + wm * 64 + mi * 16 + grp;
#pragma unroll
        for (int ni = 0; ni < 4; ni++) {
            int c = n0 + wn * 32 + ni * 8 + (four << 1);
            float b0 = bias[c], b1 = bias[c + 1];
            if (HALF_OUT) {
                __half* C = (__half*)Cv;
                *(__half2*)(C + (size_t)r * D_MODEL + c) =
                    __floats2half2_rn(acc[mi][ni][0] + b0, acc[mi][ni][1] + b1);
                *(__half2*)(C + (size_t)(r + 8) * D_MODEL + c) =
                    __floats2half2_rn(acc[mi][ni][2] + b0, acc[mi][ni][3] + b1);
            } else {
                float* C = (float*)Cv;
                float2 v0; v0.x = acc[mi][ni][0] + b0; v0.y = acc[mi][ni][1] + b1;
                float2 v1; v1.x = acc[mi][ni][2] + b0; v1.y = acc[mi][ni][3] + b1;
                *(float2*)(C + (size_t)r * D_MODEL + c)       = v0;
                *(float2*)(C + (size_t)(r + 8) * D_MODEL + c) = v1;
            }
        }
    }
}

__global__ __launch_bounds__(256, 2) void qkv_gemm_kernel(
    const float* __restrict__ bq, const float* __restrict__ bk, const float* __restrict__ bv) {
    if (blockIdx.z == 0)      gemm_body<true>(g_xh, g_Wqh, bq, g_Qh);
    else if (blockIdx.z == 1) gemm_body<true>(g_xh, g_Wkh, bk, g_Kh);
    else                      gemm_body<true>(g_xh, g_Wvh, bv, g_Vh);
}
__global__ __launch_bounds__(256, 2) void out_gemm_kernel(
    const float* __restrict__ bo, float* __restrict__ out) {
    gemm_body<false>(g_AOh, g_Woh, bo, out);
}

// ---------------- attention v9: register diet -> 3 CTAs/SM ----------------------
// 4 warps x 32 q-rows, 128-q tiles. Q frags in regs; Of in padded smem;
// QK restructured ni-pair-outer (sc = 16 regs). Single-buffered K/V.
// smem: K 8K @0, V 8K @8192, P 16K @16384 (Q staged here), Of 128x66 f32 @32768.
#define KSB 0
#define VSB 8192
#define PSB 16384
#define OFB 32768
#define OFPAD 66
#define ATTN_SMEM (32768 + 128 * OFPAD * 4)   // 66560 B; x3 CTAs = 195 KB

__global__ __launch_bounds__(128, 3) void attn_kernel(const float* __restrict__ dbias) {
    extern __shared__ __align__(128) char smc[];
    const uint32_t sb = (uint32_t)__cvta_generic_to_shared(smc);
    const int h = blockIdx.x, q0 = blockIdx.y * 128;
    const int tid = threadIdx.x, warp = tid >> 5, lane = tid & 31;
    const int grp = lane >> 2, four = lane & 3;
    const int mb = warp * 32;

    const int lr = tid >> 3, lj = tid & 7;       // loader: row, chunk

    // stage Q tile (128 rows x 128B) into the P region
#pragma unroll
    for (int i = 0; i < 8; i++) {
        int r = lr + i * 16;
        CP16(swad(sb + PSB, r, lj), g_Qh + (size_t)(q0 + r) * D_MODEL + h * 64 + lj * 8);
    }
    CPC;

    // zero Of accumulator region (128 x OFPAD f32)
    {
        float* of = (float*)(smc + OFB);
        for (int i = tid; i < 128 * OFPAD; i += 128) of[i] = 0.f;
    }

    CPW(0);
    __syncthreads();

    const int arow0 = mb + (lane & 15);          // + mi*16 ; A-frag rows (Q and P)
    const int acho  = lane >> 4;
    const int brow0f = ((lane >> 4) << 3) + (lane & 7);  // + p*16 ; B-frag rows (K,V)
    const int bcho  = (lane >> 3) & 1;

    // hoist Q fragments to registers (reused for all 32 chunks)
    uint32_t qf[2][4][4];
#pragma unroll
    for (int mi = 0; mi < 2; mi++)
#pragma unroll
        for (int g = 0; g < 4; g++)
            ldsm4(qf[mi][g], swad(sb + PSB, arow0 + mi * 16, g * 2 + acho));
    __syncthreads();                             // all Q reads done before P overwrites

    float Or[2][8][4];
#pragma unroll
    for (int mi = 0; mi < 2; mi++)
#pragma unroll
        for (int ni = 0; ni < 8; ni++)
#pragma unroll
            for (int j = 0; j < 4; j++) Or[mi][ni][j] = 0.f;
    float lsum[2][2] = {{0.f, 0.f}, {0.f, 0.f}};

    const float* brow[2][2];
#pragma unroll
    for (int mi = 0; mi < 2; mi++) {
        brow[mi][0] = dbias + (size_t)(q0 + mb + mi * 16 + grp) * N_SEQ;
        brow[mi][1] = brow[mi][0] + (size_t)8 * N_SEQ;
    }

#pragma unroll 1
    for (int kc = 0; kc < 32; kc++) {
        const int key0 = kc * 64;
        __syncthreads();                         // prior chunk fully consumed
#pragma unroll
        for (int i = 0; i < 4; i++) {
            int r = lr + i * 16;
            CP16(swad(sb + KSB, r, lj), g_Kh + (size_t)(key0 + r) * D_MODEL + h * 64 + lj * 8);
        }
        CPC;
#pragma unroll
        for (int i = 0; i < 4; i++) {
            int r = lr + i * 16;
            CP16(swad(sb + VSB, r, lj), g_Vth + (size_t)(h * 64 + r) * N_SEQ + key0 + lj * 8);
        }
        CPC;
        CPW(1);                                  // K ready; V pending
        __syncthreads();

        // QK + softmax, ni-pair-outer: sc is only 16 regs per slice
#pragma unroll
        for (int p = 0; p < 4; p++) {
            float sc[2][2][4];
#pragma unroll
            for (int mi = 0; mi < 2; mi++)
#pragma unroll
                for (int t = 0; t < 2; t++)
#pragma unroll
                    for (int j = 0; j < 4; j++) sc[mi][t][j] = 0.f;
#pragma unroll
            for (int g = 0; g < 4; g++) {
                uint32_t bb[4];
                ldsm4(bb, swad(sb + KSB, p * 16 + brow0f, g * 2 + bcho));
#pragma unroll
                for (int mi = 0; mi < 2; mi++) {
                    mma_f16(sc[mi][0], qf[mi][g], &bb[0]);
                    mma_f16(sc[mi][1], qf[mi][g], &bb[2]);
                }
            }
            // softmax slice ni = 2p, 2p+1 ; P staged to smem (fp16)
#pragma unroll
            for (int mi = 0; mi < 2; mi++) {
                const int rA = mb + mi * 16 + grp, rB = rA + 8;
#pragma unroll
                for (int t = 0; t < 2; t++) {
                    const int ni = 2 * p + t;
                    const int c = ni * 8 + (four << 1);
                    float2 bA = *(const float2*)(brow[mi][0] + key0 + c);
                    float2 bB = *(const float2*)(brow[mi][1] + key0 + c);
                    float p0 = __expf(fmaf(sc[mi][t][0], ATTN_SCALE, -bA.x));
                    float p1 = __expf(fmaf(sc[mi][t][1], ATTN_SCALE, -bA.y));
                    float p2 = __expf(fmaf(sc[mi][t][2], ATTN_SCALE, -bB.x));
                    float p3 = __expf(fmaf(sc[mi][t][3], ATTN_SCALE, -bB.y));
                    lsum[mi][0] += p0 + p1; lsum[mi][1] += p2 + p3;
                    *(uint32_t*)(smc + PSB + rA * 128 + (((ni) ^ (rA & 7)) << 4) + four * 4) = packh2(p0, p1);
                    *(uint32_t*)(smc + PSB + rB * 128 + (((ni) ^ (rB & 7)) << 4) + four * 4) = packh2(p2, p3);
                }
            }
        }
        __syncwarp();                            // own-warp P rows visible

        CPW(0);                                  // V arrived
        __syncthreads();                         // V visible CTA-wide

        // Or += P @ V
#pragma unroll
        for (int g = 0; g < 4; g++) {
            uint32_t a[2][4], bb[4][4];
#pragma unroll
            for (int mi = 0; mi < 2; mi++)
                ldsm4(a[mi], swad(sb + PSB, arow0 + mi * 16, g * 2 + acho));
#pragma unroll
            for (int p = 0; p < 4; p++)
                ldsm4(bb[p], swad(sb + VSB, brow0f + p * 16, g * 2 + bcho));
#pragma unroll
            for (int mi = 0; mi < 2; mi++)
#pragma unroll
                for (int ni = 0; ni < 8; ni++)
                    mma_f16(Or[mi][ni], a[mi], &bb[ni >> 1][(ni & 1) << 1]);
        }

        // 256-key block boundary: normalize into smem Of, reset Or
        if ((kc & 3) == 3) {
#pragma unroll
            for (int mi = 0; mi < 2; mi++) {
                float L0 = lsum[mi][0], L1 = lsum[mi][1];
                L0 += __shfl_xor_sync(0xffffffffu, L0, 1);
                L0 += __shfl_xor_sync(0xffffffffu, L0, 2);
                L1 += __shfl_xor_sync(0xffffffffu, L1, 1);
                L1 += __shfl_xor_sync(0xffffffffu, L1, 2);
                float i0 = 1.0f / L0, i1 = 1.0f / L1;
                float* of0 = (float*)(smc + OFB) + (mb + mi * 16 + grp) * OFPAD;
                float* of1 = of0 + 8 * OFPAD;
#pragma unroll
                for (int ni = 0; ni < 8; ni++) {
                    const int c = ni * 8 + (four << 1);
                    of0[c]     += Or[mi][ni][0] * i0;
                    of0[c + 1] += Or[mi][ni][1] * i0;
                    of1[c]     += Or[mi][ni][2] * i1;
                    of1[c + 1] += Or[mi][ni][3] * i1;
                    Or[mi][ni][0] = Or[mi][ni][1] = Or[mi][ni][2] = Or[mi][ni][3] = 0.f;
                }
                lsum[mi][0] = 0.f; lsum[mi][1] = 0.f;
            }
        }
    }

    const float r8 = 1.0f / (8.0f + 1e-8f);      // exact normalizer: nb = 8
#pragma unroll
    for (int mi = 0; mi < 2; mi++) {
        const float* of0 = (const float*)(smc + OFB) + (mb + mi * 16 + grp) * OFPAD;
        const float* of1 = of0 + 8 * OFPAD;
#pragma unroll
        for (int ni = 0; ni < 8; ni++) {
            int c = ni * 8 + (four << 1);
            int cg = h * 64 + c;
            size_t o0 = (size_t)(q0 + mb + mi * 16 + grp) * D_MODEL + cg;
            size_t o1 = o0 + (size_t)8 * D_MODEL;
            *(__half2*)(g_AOh + o0) = __floats2half2_rn(of0[c] * r8, of0[c + 1] * r8);
            *(__half2*)(g_AOh + o1) = __floats2half2_rn(of1[c] * r8, of1[c + 1] * r8);
        }
    }
}

// ---------------- launch ---------------------------------------------------------
extern "C" void kernel_launch(void* const* d_in, const int* in_sizes, int n_in,
                              void* d_out, int out_size) {
    const float* x  = (const float*)d_in[0];
    const float* db = (const float*)d_in[1];
    const float* Wq = (const float*)d_in[2];
    const float* bq = (const float*)d_in[3];
    const float* Wk = (const float*)d_in[4];
    const float* bk = (const float*)d_in[5];
    const float* Wv = (const float*)d_in[6];
    const float* bv = (const float*)d_in[7];
    const float* Wo = (const float*)d_in[8];
    const float* bo = (const float*)d_in[9];
    float* out = (float*)d_out;

    cudaFuncSetAttribute(qkv_gemm_kernel, cudaFuncAttributeMaxDynamicSharedMemorySize, GEMM_SMEM);
    cudaFuncSetAttribute(out_gemm_kernel, cudaFuncAttributeMaxDynamicSharedMemorySize, GEMM_SMEM);
    cudaFuncSetAttribute(attn_kernel,     cudaFuncAttributeMaxDynamicSharedMemorySize, ATTN_SMEM);

    prep_kernel<<<dim3(2048, 5), 256>>>((const float4*)x, (const float4*)Wq,
                                        (const float4*)Wk, (const float4*)Wv,
                                        (const float4*)Wo);
    qkv_gemm_kernel<<<dim3(16, 8, 3), 256, GEMM_SMEM>>>(bq, bk, bv);
    transposeV_kernel<<<dim3(32, 64), 256>>>();
    attn_kernel<<<dim3(16, 16), 128, ATTN_SMEM>>>(db);
    out_gemm_kernel<<<dim3(16, 8), 256, GEMM_SMEM>>>(bo, out);
}

// round 15
// speedup vs baseline: 1.2713x; 1.2713x over previous
#include <cuda_runtime.h>
#include <cuda_fp16.h>
#include <cstdint>

#define N_SEQ   2048
#define D_MODEL 1024
#define ATTN_SCALE 0.125f

// ---------------- scratch (fp16 operands, fp32 accumulation everywhere) -------
__device__ __half g_xh [N_SEQ * D_MODEL];
__device__ __half g_Wqh[D_MODEL * D_MODEL];
__device__ __half g_Wkh[D_MODEL * D_MODEL];
__device__ __half g_Wvh[D_MODEL * D_MODEL];
__device__ __half g_Woh[D_MODEL * D_MODEL];
__device__ __half g_Qh [N_SEQ * D_MODEL];
__device__ __half g_Kh [N_SEQ * D_MODEL];
__device__ __half g_Vh [N_SEQ * D_MODEL];
__device__ __half g_Vth[D_MODEL * N_SEQ];     // transposed V, [d][token]
__device__ __half g_AOh[N_SEQ * D_MODEL];

// ---------------- helpers ------------------------------------------------------
__device__ __forceinline__ void mma_f16(float c[4], const uint32_t a[4], const uint32_t b[2]) {
    asm volatile(
        "mma.sync.aligned.m16n8k16.row.col.f32.f16.f16.f32 "
        "{%0,%1,%2,%3}, {%4,%5,%6,%7}, {%8,%9}, {%0,%1,%2,%3};\n"
        : "+f"(c[0]), "+f"(c[1]), "+f"(c[2]), "+f"(c[3])
        : "r"(a[0]), "r"(a[1]), "r"(a[2]), "r"(a[3]), "r"(b[0]), "r"(b[1]));
}
__device__ __forceinline__ void ldsm4(uint32_t r[4], uint32_t addr) {
    asm volatile("ldmatrix.sync.aligned.m8n8.x4.shared.b16 {%0,%1,%2,%3}, [%4];"
                 : "=r"(r[0]), "=r"(r[1]), "=r"(r[2]), "=r"(r[3]) : "r"(addr));
}
#define CP16(dst, src) asm volatile("cp.async.cg.shared.global [%0], [%1], 16;" :: "r"(dst), "l"(src))
#define CPC            asm volatile("cp.async.commit_group;")
#define CPW(n)         asm volatile("cp.async.wait_group %0;" :: "n"(n))

// swizzled byte address: 128B rows, 8 x 16B chunks, chunk ^= (row & 7)
__device__ __forceinline__ uint32_t swad(uint32_t base, int row, int chunk) {
    return base + row * 128 + (((chunk) ^ (row & 7)) << 4);
}
__device__ __forceinline__ uint32_t packh2(float a, float b) {
    __half2 h = __floats2half2_rn(a, b);
    return *(uint32_t*)&h;
}

// ---------------- prep: f32 -> fp16 --------------------------------------------
__global__ __launch_bounds__(256) void prep_kernel(
    const float4* __restrict__ x,
    const float4* __restrict__ Wq, const float4* __restrict__ Wk,
    const float4* __restrict__ Wv, const float4* __restrict__ Wo) {
    const float4* src; __half2* dst; int n4;
    switch (blockIdx.y) {
        case 0:  src = x;  dst = (__half2*)g_xh;  n4 = 524288; break;
        case 1:  src = Wq; dst = (__half2*)g_Wqh; n4 = 262144; break;
        case 2:  src = Wk; dst = (__half2*)g_Wkh; n4 = 262144; break;
        case 3:  src = Wv; dst = (__half2*)g_Wvh; n4 = 262144; break;
        default: src = Wo; dst = (__half2*)g_Woh; n4 = 262144; break;
    }
    int i = blockIdx.x * 256 + threadIdx.x;
    if (i < n4) {
        float4 v = src[i];
        dst[2 * i]     = __floats2half2_rn(v.x, v.y);
        dst[2 * i + 1] = __floats2half2_rn(v.z, v.w);
    }
}

// ---------------- V transpose (half) --------------------------------------------
__global__ __launch_bounds__(256) void transposeV_kernel() {
    __shared__ __half t[32][33];
    const int tx = threadIdx.x & 31, ty = threadIdx.x >> 5;
    const int bx = blockIdx.x, by = blockIdx.y;
#pragma unroll
    for (int j = 0; j < 4; j++)
        t[ty + j * 8][tx] = g_Vh[(size_t)(by * 32 + ty + j * 8) * D_MODEL + bx * 32 + tx];
    __syncthreads();
#pragma unroll
    for (int j = 0; j < 4; j++)
        g_Vth[(size_t)(bx * 32 + ty + j * 8) * N_SEQ + by * 32 + tx] = t[tx][ty + j * 8];
}

// ---------------- GEMM fp16 (R8, proven): C = A @ W^T + bias --------------------
#define G_A(s)  ((s) * 16384)
#define G_B(s)  (32768 + (s) * 16384)
#define GEMM_SMEM 65536

template <bool HALF_OUT>
__device__ __forceinline__ void gemm_body(const __half* __restrict__ A, const __half* __restrict__ W,
                                          const float* __restrict__ bias, void* __restrict__ Cv) {
    extern __shared__ __align__(128) char smc[];
    const uint32_t sb = (uint32_t)__cvta_generic_to_shared(smc);
    const int tid = threadIdx.x, warp = tid >> 5, lane = tid & 31;
    const int grp = lane >> 2, four = lane & 3;
    const int wm = warp >> 2, wn = warp & 3;
    const int m0 = blockIdx.x * 128, n0 = blockIdx.y * 128;

    float acc[4][4][4];
#pragma unroll
    for (int mi = 0; mi < 4; mi++)
#pragma unroll
        for (int ni = 0; ni < 4; ni++)
#pragma unroll
            for (int j = 0; j < 4; j++) acc[mi][ni][j] = 0.f;

    const int lr = tid >> 3, lj = tid & 7;

    const int arow = wm * 64 + (lane & 15);
    const int acho = lane >> 4;
    const int brow = wn * 32 + ((lane >> 4) << 3) + (lane & 7);
    const int bcho = (lane >> 3) & 1;

#pragma unroll 1
    for (int kt = -1; kt < 16; kt++) {
        if (kt < 15) {
            const int s = (kt + 1) & 1, k0 = (kt + 1) * 64;
#pragma unroll
            for (int i = 0; i < 4; i++) {
                int r = lr + i * 32;
                CP16(swad(sb + G_A(s), r, lj), A + (size_t)(m0 + r) * D_MODEL + k0 + lj * 8);
                CP16(swad(sb + G_B(s), r, lj), W + (size_t)(n0 + r) * D_MODEL + k0 + lj * 8);
            }
            CPC;
        }
        if (kt < 0) continue;
        if (kt < 15) { CPW(1); } else { CPW(0); }
        __syncthreads();

        const int s = kt & 1;
        const uint32_t ab = sb + G_A(s), bbs = sb + G_B(s);
#pragma unroll
        for (int g = 0; g < 4; g++) {
            uint32_t a[4][4], bb[2][4];
#pragma unroll
            for (int mi = 0; mi < 4; mi++)
                ldsm4(a[mi], swad(ab, arow + mi * 16, g * 2 + acho));
#pragma unroll
            for (int p = 0; p < 2; p++)
                ldsm4(bb[p], swad(bbs, brow + p * 16, g * 2 + bcho));
#pragma unroll
            for (int mi = 0; mi < 4; mi++)
#pragma unroll
                for (int ni = 0; ni < 4; ni++)
                    mma_f16(acc[mi][ni], a[mi], &bb[ni >> 1][(ni & 1) << 1]);
        }
        __syncthreads();
    }

#pragma unroll
    for (int mi = 0; mi < 4; mi++) {
        int r = m0 + wm * 64 + mi * 16 + grp;
#pragma unroll
        for (int ni = 0; ni < 4; ni++) {
            int c = n0 + wn * 32 + ni * 8 + (four << 1);
            float b0 = bias[c], b1 = bias[c + 1];
            if (HALF_OUT) {
                __half* C = (__half*)Cv;
                *(__half2*)(C + (size_t)r * D_MODEL + c) =
                    __floats2half2_rn(acc[mi][ni][0] + b0, acc[mi][ni][1] + b1);
                *(__half2*)(C + (size_t)(r + 8) * D_MODEL + c) =
                    __floats2half2_rn(acc[mi][ni][2] + b0, acc[mi][ni][3] + b1);
            } else {
                float* C = (float*)Cv;
                float2 v0; v0.x = acc[mi][ni][0] + b0; v0.y = acc[mi][ni][1] + b1;
                float2 v1; v1.x = acc[mi][ni][2] + b0; v1.y = acc[mi][ni][3] + b1;
                *(float2*)(C + (size_t)r * D_MODEL + c)       = v0;
                *(float2*)(C + (size_t)(r + 8) * D_MODEL + c) = v1;
            }
        }
    }
}

__global__ __launch_bounds__(256, 2) void qkv_gemm_kernel(
    const float* __restrict__ bq, const float* __restrict__ bk, const float* __restrict__ bv) {
    if (blockIdx.z == 0)      gemm_body<true>(g_xh, g_Wqh, bq, g_Qh);
    else if (blockIdx.z == 1) gemm_body<true>(g_xh, g_Wkh, bk, g_Kh);
    else                      gemm_body<true>(g_xh, g_Wvh, bv, g_Vh);
}
__global__ __launch_bounds__(256, 2) void out_gemm_kernel(
    const float* __restrict__ bo, float* __restrict__ out) {
    gemm_body<false>(g_AOh, g_Woh, bo, out);
}

// ---------------- attention v11b: one-chunk skew, fixed P slot size -------------
// 4 warps x 32 q-rows, 128-q tiles. smem: Q 16K @0, K[2] 8K @16384/24576,
// V[2] 8K @32768/40960, P[2] 16K @49152/65536 = 80K. 2 CTAs/SM (160K <= 228K).
#define QSB 0
#define KSB(s) (16384 + (s) * 8192)
#define VSB(s) (32768 + (s) * 8192)
#define PSB(s) (49152 + (s) * 16384)
#define ATTN_SMEM 81920

__global__ __launch_bounds__(128, 2) void attn_kernel(const float* __restrict__ dbias) {
    extern __shared__ __align__(128) char smc[];
    const uint32_t sb = (uint32_t)__cvta_generic_to_shared(smc);
    const int h = blockIdx.x, q0 = blockIdx.y * 128;
    const int tid = threadIdx.x, warp = tid >> 5, lane = tid & 31;
    const int grp = lane >> 2, four = lane & 3;
    const int mb = warp * 32;

    const int lr = tid >> 3, lj = tid & 7;       // loader: row, chunk

    // prologue loads: G0{Q}, G1{K0}, G2{K1,V0}
#pragma unroll
    for (int i = 0; i < 8; i++) {
        int r = lr + i * 16;
        CP16(swad(sb + QSB, r, lj), g_Qh + (size_t)(q0 + r) * D_MODEL + h * 64 + lj * 8);
    }
    CPC;
#pragma unroll
    for (int i = 0; i < 4; i++) {
        int r = lr + i * 16;
        CP16(swad(sb + KSB(0), r, lj), g_Kh + (size_t)(r) * D_MODEL + h * 64 + lj * 8);
    }
    CPC;
#pragma unroll
    for (int i = 0; i < 4; i++) {
        int r = lr + i * 16;
        CP16(swad(sb + KSB(1), r, lj), g_Kh  + (size_t)(64 + r) * D_MODEL + h * 64 + lj * 8);
        CP16(swad(sb + VSB(0), r, lj), g_Vth + (size_t)(h * 64 + r) * N_SEQ + 0 + lj * 8);
    }
    CPC;
    CPW(1);                                      // Q + K0 ready
    __syncthreads();

    float Of[2][8][4], Or[2][8][4];
#pragma unroll
    for (int mi = 0; mi < 2; mi++)
#pragma unroll
        for (int ni = 0; ni < 8; ni++)
#pragma unroll
            for (int j = 0; j < 4; j++) { Of[mi][ni][j] = 0.f; Or[mi][ni][j] = 0.f; }
    float lsum[2][2] = {{0.f, 0.f}, {0.f, 0.f}};
    float lsP[2][2]  = {{0.f, 0.f}, {0.f, 0.f}};

    const float* brow[2][2];
#pragma unroll
    for (int mi = 0; mi < 2; mi++) {
        brow[mi][0] = dbias + (size_t)(q0 + mb + mi * 16 + grp) * N_SEQ;
        brow[mi][1] = brow[mi][0] + (size_t)8 * N_SEQ;
    }

    const int arow0 = mb + (lane & 15);          // + mi*16 ; A-frag rows (Q and P)
    const int acho  = lane >> 4;
    const int brow0f = ((lane >> 4) << 3) + (lane & 7);  // + p*16 ; B-frag rows (K,V)
    const int bcho  = (lane >> 3) & 1;

#pragma unroll 1
    for (int kc = 0; kc < 32; kc++) {
        const int key0 = kc * 64;
        const int s  = kc & 1;                   // slot for K(kc), P(kc)
        const int sp = s ^ 1;                    // slot for V(kc-1), P(kc-1)

        // block boundary bookkeeping: softmax runs 1 chunk ahead of PV
        if (kc && (kc & 3) == 0) {
#pragma unroll
            for (int mi = 0; mi < 2; mi++) {
                lsP[mi][0] = lsum[mi][0]; lsP[mi][1] = lsum[mi][1];
                lsum[mi][0] = 0.f; lsum[mi][1] = 0.f;
            }
        }

        // ---- QK(kc): sc = Q @ K(kc)^T ----
        float sc[2][8][4];
#pragma unroll
        for (int mi = 0; mi < 2; mi++)
#pragma unroll
            for (int ni = 0; ni < 8; ni++)
#pragma unroll
                for (int j = 0; j < 4; j++) sc[mi][ni][j] = 0.f;
#pragma unroll
        for (int g = 0; g < 4; g++) {
            uint32_t a[2][4], bb[4][4];
#pragma unroll
            for (int mi = 0; mi < 2; mi++)
                ldsm4(a[mi], swad(sb + QSB, arow0 + mi * 16, g * 2 + acho));
#pragma unroll
            for (int p = 0; p < 4; p++)
                ldsm4(bb[p], swad(sb + KSB(s), brow0f + p * 16, g * 2 + bcho));
#pragma unroll
            for (int mi = 0; mi < 2; mi++)
#pragma unroll
                for (int ni = 0; ni < 8; ni++)
                    mma_f16(sc[mi][ni], a[mi], &bb[ni >> 1][(ni & 1) << 1]);
        }

        // ---- mixed block: softmax(kc) -> P[s]  ||  PV(kc-1) from P[sp],V[sp] ----
#pragma unroll
        for (int mi = 0; mi < 2; mi++) {
            const int rA = mb + mi * 16 + grp, rB = rA + 8;
#pragma unroll
            for (int ni = 0; ni < 8; ni++) {
                int c = ni * 8 + (four << 1);
                float2 bA = *(const float2*)(brow[mi][0] + key0 + c);
                float2 bB = *(const float2*)(brow[mi][1] + key0 + c);
                float p0 = __expf(fmaf(sc[mi][ni][0], ATTN_SCALE, -bA.x));
                float p1 = __expf(fmaf(sc[mi][ni][1], ATTN_SCALE, -bA.y));
                float p2 = __expf(fmaf(sc[mi][ni][2], ATTN_SCALE, -bB.x));
                float p3 = __expf(fmaf(sc[mi][ni][3], ATTN_SCALE, -bB.y));
                lsum[mi][0] += p0 + p1; lsum[mi][1] += p2 + p3;
                *(uint32_t*)(smc + PSB(s) + rA * 128 + (((ni) ^ (rA & 7)) << 4) + four * 4) = packh2(p0, p1);
                *(uint32_t*)(smc + PSB(s) + rB * 128 + (((ni) ^ (rB & 7)) << 4) + four * 4) = packh2(p2, p3);
            }
        }
        if (kc > 0) {
#pragma unroll
            for (int g = 0; g < 4; g++) {
                uint32_t a[2][4], bb[4][4];
#pragma unroll
                for (int mi = 0; mi < 2; mi++)
                    ldsm4(a[mi], swad(sb + PSB(sp), arow0 + mi * 16, g * 2 + acho));
#pragma unroll
                for (int p = 0; p < 4; p++)
                    ldsm4(bb[p], swad(sb + VSB(sp), brow0f + p * 16, g * 2 + bcho));
#pragma unroll
                for (int mi = 0; mi < 2; mi++)
#pragma unroll
                    for (int ni = 0; ni < 8; ni++)
                        mma_f16(Or[mi][ni], a[mi], &bb[ni >> 1][(ni & 1) << 1]);
            }
        }
        __syncwarp();                            // P[s] stores visible for next iter

        // boundary for block (kc/4 - 1): Or now holds that block's full PV
        if (kc && (kc & 3) == 0) {
#pragma unroll
            for (int mi = 0; mi < 2; mi++) {
                float L0 = lsP[mi][0], L1 = lsP[mi][1];
                L0 += __shfl_xor_sync(0xffffffffu, L0, 1);
                L0 += __shfl_xor_sync(0xffffffffu, L0, 2);
                L1 += __shfl_xor_sync(0xffffffffu, L1, 1);
                L1 += __shfl_xor_sync(0xffffffffu, L1, 2);
                float i0 = 1.0f / L0, i1 = 1.0f / L1;
#pragma unroll
                for (int ni = 0; ni < 8; ni++) {
                    Of[mi][ni][0] += Or[mi][ni][0] * i0;
                    Of[mi][ni][1] += Or[mi][ni][1] * i0;
                    Of[mi][ni][2] += Or[mi][ni][2] * i1;
                    Of[mi][ni][3] += Or[mi][ni][3] * i1;
                    Or[mi][ni][0] = Or[mi][ni][1] = Or[mi][ni][2] = Or[mi][ni][3] = 0.f;
                }
            }
        }

        // refill: K(kc+2) -> slot s (K(kc) dead), V(kc+1) -> slot sp (V(kc-1) dead)
        __syncthreads();
        if (kc <= 29) {
            const int nk = key0 + 128;
#pragma unroll
            for (int i = 0; i < 4; i++) {
                int r = lr + i * 16;
                CP16(swad(sb + KSB(s), r, lj), g_Kh + (size_t)(nk + r) * D_MODEL + h * 64 + lj * 8);
            }
        }
        if (kc <= 30) {
            const int nv = key0 + 64;
#pragma unroll
            for (int i = 0; i < 4; i++) {
                int r = lr + i * 16;
                CP16(swad(sb + VSB(sp), r, lj), g_Vth + (size_t)(h * 64 + r) * N_SEQ + nv + lj * 8);
            }
        }
        CPC;                                      // (possibly empty group near tail)
        CPW(1);                                   // K(kc+1) + V(kc) complete
        __syncthreads();
    }

    // tail: PV(31) + final block boundary (block 7)
#pragma unroll
    for (int mi = 0; mi < 2; mi++) { lsP[mi][0] = lsum[mi][0]; lsP[mi][1] = lsum[mi][1]; }
#pragma unroll
    for (int g = 0; g < 4; g++) {
        uint32_t a[2][4], bb[4][4];
#pragma unroll
        for (int mi = 0; mi < 2; mi++)
            ldsm4(a[mi], swad(sb + PSB(1), arow0 + mi * 16, g * 2 + acho));
#pragma unroll
        for (int p = 0; p < 4; p++)
            ldsm4(bb[p], swad(sb + VSB(1), brow0f + p * 16, g * 2 + bcho));
#pragma unroll
        for (int mi = 0; mi < 2; mi++)
#pragma unroll
            for (int ni = 0; ni < 8; ni++)
                mma_f16(Or[mi][ni], a[mi], &bb[ni >> 1][(ni & 1) << 1]);
    }
#pragma unroll
    for (int mi = 0; mi < 2; mi++) {
        float L0 = lsP[mi][0], L1 = lsP[mi][1];
        L0 += __shfl_xor_sync(0xffffffffu, L0, 1);
        L0 += __shfl_xor_sync(0xffffffffu, L0, 2);
        L1 += __shfl_xor_sync(0xffffffffu, L1, 1);
        L1 += __shfl_xor_sync(0xffffffffu, L1, 2);
        float i0 = 1.0f / L0, i1 = 1.0f / L1;
#pragma unroll
        for (int ni = 0; ni < 8; ni++) {
            Of[mi][ni][0] += Or[mi][ni][0] * i0;
            Of[mi][ni][1] += Or[mi][ni][1] * i0;
            Of[mi][ni][2] += Or[mi][ni][2] * i1;
            Of[mi][ni][3] += Or[mi][ni][3] * i1;
        }
    }

    const float r8 = 1.0f / (8.0f + 1e-8f);      // exact normalizer: nb = 8
#pragma unroll
    for (int mi = 0; mi < 2; mi++) {
#pragma unroll
        for (int ni = 0; ni < 8; ni++) {
            int c = h * 64 + ni * 8 + (four << 1);
            size_t o0 = (size_t)(q0 + mb + mi * 16 + grp) * D_MODEL + c;
            size_t o1 = o0 + (size_t)8 * D_MODEL;
            *(__half2*)(g_AOh + o0) = __floats2half2_rn(Of[mi][ni][0] * r8, Of[mi][ni][1] * r8);
            *(__half2*)(g_AOh + o1) = __floats2half2_rn(Of[mi][ni][2] * r8, Of[mi][ni][3] * r8);
        }
    }
}

// ---------------- launch ---------------------------------------------------------
extern "C" void kernel_launch(void* const* d_in, const int* in_sizes, int n_in,
                              void* d_out, int out_size) {
    const float* x  = (const float*)d_in[0];
    const float* db = (const float*)d_in[1];
    const float* Wq = (const float*)d_in[2];
    const float* bq = (const float*)d_in[3];
    const float* Wk = (const float*)d_in[4];
    const float* bk = (const float*)d_in[5];
    const float* Wv = (const float*)d_in[6];
    const float* bv = (const float*)d_in[7];
    const float* Wo = (const float*)d_in[8];
    const float* bo = (const float*)d_in[9];
    float* out = (float*)d_out;

    cudaFuncSetAttribute(qkv_gemm_kernel, cudaFuncAttributeMaxDynamicSharedMemorySize, GEMM_SMEM);
    cudaFuncSetAttribute(out_gemm_kernel, cudaFuncAttributeMaxDynamicSharedMemorySize, GEMM_SMEM);
    cudaFuncSetAttribute(attn_kernel,     cudaFuncAttributeMaxDynamicSharedMemorySize, ATTN_SMEM);

    prep_kernel<<<dim3(2048, 5), 256>>>((const float4*)x, (const float4*)Wq,
                                        (const float4*)Wk, (const float4*)Wv,
                                        (const float4*)Wo);
    qkv_gemm_kernel<<<dim3(16, 8, 3), 256, GEMM_SMEM>>>(bq, bk, bv);
    transposeV_kernel<<<dim3(32, 64), 256>>>();
    attn_kernel<<<dim3(16, 16), 128, ATTN_SMEM>>>(db);
    out_gemm_kernel<<<dim3(16, 8), 256, GEMM_SMEM>>>(bo, out);
}

// round 16
// speedup vs baseline: 1.3372x; 1.0519x over previous
#include <cuda_runtime.h>
#include <cuda_fp16.h>
#include <cstdint>

#define N_SEQ   2048
#define D_MODEL 1024
#define ATTN_SCALE 0.125f

// ---------------- scratch (fp16 operands, fp32 accumulation everywhere) -------
__device__ __half g_xh [N_SEQ * D_MODEL];
__device__ __half g_Wqh[D_MODEL * D_MODEL];
__device__ __half g_Wkh[D_MODEL * D_MODEL];
__device__ __half g_Wvh[D_MODEL * D_MODEL];
__device__ __half g_Woh[D_MODEL * D_MODEL];
__device__ __half g_Qh [N_SEQ * D_MODEL];
__device__ __half g_Kh [N_SEQ * D_MODEL];
__device__ __half g_Vth[D_MODEL * N_SEQ];     // transposed V, [d][token] (written directly by qkv)
__device__ __half g_AOh[N_SEQ * D_MODEL];

// ---------------- helpers ------------------------------------------------------
__device__ __forceinline__ void mma_f16(float c[4], const uint32_t a[4], const uint32_t b[2]) {
    asm volatile(
        "mma.sync.aligned.m16n8k16.row.col.f32.f16.f16.f32 "
        "{%0,%1,%2,%3}, {%4,%5,%6,%7}, {%8,%9}, {%0,%1,%2,%3};\n"
        : "+f"(c[0]), "+f"(c[1]), "+f"(c[2]), "+f"(c[3])
        : "r"(a[0]), "r"(a[1]), "r"(a[2]), "r"(a[3]), "r"(b[0]), "r"(b[1]));
}
__device__ __forceinline__ void ldsm4(uint32_t r[4], uint32_t addr) {
    asm volatile("ldmatrix.sync.aligned.m8n8.x4.shared.b16 {%0,%1,%2,%3}, [%4];"
                 : "=r"(r[0]), "=r"(r[1]), "=r"(r[2]), "=r"(r[3]) : "r"(addr));
}
#define CP16(dst, src) asm volatile("cp.async.cg.shared.global [%0], [%1], 16;" :: "r"(dst), "l"(src))
#define CPC            asm volatile("cp.async.commit_group;")
#define CPW(n)         asm volatile("cp.async.wait_group %0;" :: "n"(n))

// swizzled byte address: 128B rows, 8 x 16B chunks, chunk ^= (row & 7)
__device__ __forceinline__ uint32_t swad(uint32_t base, int row, int chunk) {
    return base + row * 128 + (((chunk) ^ (row & 7)) << 4);
}
__device__ __forceinline__ uint32_t packh2(float a, float b) {
    __half2 h = __floats2half2_rn(a, b);
    return *(uint32_t*)&h;
}

// ---------------- prep: f32 -> fp16 --------------------------------------------
__global__ __launch_bounds__(256) void prep_kernel(
    const float4* __restrict__ x,
    const float4* __restrict__ Wq, const float4* __restrict__ Wk,
    const float4* __restrict__ Wv, const float4* __restrict__ Wo) {
    const float4* src; __half2* dst; int n4;
    switch (blockIdx.y) {
        case 0:  src = x;  dst = (__half2*)g_xh;  n4 = 524288; break;
        case 1:  src = Wq; dst = (__half2*)g_Wqh; n4 = 262144; break;
        case 2:  src = Wk; dst = (__half2*)g_Wkh; n4 = 262144; break;
        case 3:  src = Wv; dst = (__half2*)g_Wvh; n4 = 262144; break;
        default: src = Wo; dst = (__half2*)g_Woh; n4 = 262144; break;
    }
    int i = blockIdx.x * 256 + threadIdx.x;
    if (i < n4) {
        float4 v = src[i];
        dst[2 * i]     = __floats2half2_rn(v.x, v.y);
        dst[2 * i + 1] = __floats2half2_rn(v.z, v.w);
    }
}

// ---------------- GEMM fp16 (R8 core): C = A @ W^T + bias -----------------------
// MODE: 0 = f32 row-major out, 1 = fp16 row-major out, 2 = fp16 TRANSPOSED out
// (mode 2 writes C^T for V so attention reads g_Vth[d][token] directly).
#define G_A(s)  ((s) * 16384)
#define G_B(s)  (32768 + (s) * 16384)
#define GEMM_SMEM 65536

template <int MODE>
__device__ __forceinline__ void gemm_body(const __half* __restrict__ A, const __half* __restrict__ W,
                                          const float* __restrict__ bias, void* __restrict__ Cv) {
    extern __shared__ __align__(128) char smc[];
    const uint32_t sb = (uint32_t)__cvta_generic_to_shared(smc);
    const int tid = threadIdx.x, warp = tid >> 5, lane = tid & 31;
    const int grp = lane >> 2, four = lane & 3;
    const int wm = warp >> 2, wn = warp & 3;
    const int m0 = blockIdx.x * 128, n0 = blockIdx.y * 128;

    float acc[4][4][4];
#pragma unroll
    for (int mi = 0; mi < 4; mi++)
#pragma unroll
        for (int ni = 0; ni < 4; ni++)
#pragma unroll
            for (int j = 0; j < 4; j++) acc[mi][ni][j] = 0.f;

    const int lr = tid >> 3, lj = tid & 7;

    const int arow = wm * 64 + (lane & 15);
    const int acho = lane >> 4;
    const int brow = wn * 32 + ((lane >> 4) << 3) + (lane & 7);
    const int bcho = (lane >> 3) & 1;

#pragma unroll 1
    for (int kt = -1; kt < 16; kt++) {
        if (kt < 15) {
            const int s = (kt + 1) & 1, k0 = (kt + 1) * 64;
#pragma unroll
            for (int i = 0; i < 4; i++) {
                int r = lr + i * 32;
                CP16(swad(sb + G_A(s), r, lj), A + (size_t)(m0 + r) * D_MODEL + k0 + lj * 8);
                CP16(swad(sb + G_B(s), r, lj), W + (size_t)(n0 + r) * D_MODEL + k0 + lj * 8);
            }
            CPC;
        }
        if (kt < 0) continue;
        if (kt < 15) { CPW(1); } else { CPW(0); }
        __syncthreads();

        const int s = kt & 1;
        const uint32_t ab = sb + G_A(s), bbs = sb + G_B(s);
#pragma unroll
        for (int g = 0; g < 4; g++) {
            uint32_t a[4][4], bb[2][4];
#pragma unroll
            for (int mi = 0; mi < 4; mi++)
                ldsm4(a[mi], swad(ab, arow + mi * 16, g * 2 + acho));
#pragma unroll
            for (int p = 0; p < 2; p++)
                ldsm4(bb[p], swad(bbs, brow + p * 16, g * 2 + bcho));
#pragma unroll
            for (int mi = 0; mi < 4; mi++)
#pragma unroll
                for (int ni = 0; ni < 4; ni++)
                    mma_f16(acc[mi][ni], a[mi], &bb[ni >> 1][(ni & 1) << 1]);
        }
        __syncthreads();
    }

#pragma unroll
    for (int mi = 0; mi < 4; mi++) {
        int r = m0 + wm * 64 + mi * 16 + grp;
#pragma unroll
        for (int ni = 0; ni < 4; ni++) {
            int c = n0 + wn * 32 + ni * 8 + (four << 1);
            float b0 = bias[c], b1 = bias[c + 1];
            if (MODE == 1) {
                __half* C = (__half*)Cv;
                *(__half2*)(C + (size_t)r * D_MODEL + c) =
                    __floats2half2_rn(acc[mi][ni][0] + b0, acc[mi][ni][1] + b1);
                *(__half2*)(C + (size_t)(r + 8) * D_MODEL + c) =
                    __floats2half2_rn(acc[mi][ni][2] + b0, acc[mi][ni][3] + b1);
            } else if (MODE == 2) {
                // transposed store: C^T[c][r]  (values identical to mode-1 rounding)
                __half* C = (__half*)Cv;
                C[(size_t)c * N_SEQ + r]           = __float2half_rn(acc[mi][ni][0] + b0);
                C[(size_t)(c + 1) * N_SEQ + r]     = __float2half_rn(acc[mi][ni][1] + b1);
                C[(size_t)c * N_SEQ + r + 8]       = __float2half_rn(acc[mi][ni][2] + b0);
                C[(size_t)(c + 1) * N_SEQ + r + 8] = __float2half_rn(acc[mi][ni][3] + b1);
            } else {
                float* C = (float*)Cv;
                float2 v0; v0.x = acc[mi][ni][0] + b0; v0.y = acc[mi][ni][1] + b1;
                float2 v1; v1.x = acc[mi][ni][2] + b0; v1.y = acc[mi][ni][3] + b1;
                *(float2*)(C + (size_t)r * D_MODEL + c)       = v0;
                *(float2*)(C + (size_t)(r + 8) * D_MODEL + c) = v1;
            }
        }
    }
}

__global__ __launch_bounds__(256, 2) void qkv_gemm_kernel(
    const float* __restrict__ bq, const float* __restrict__ bk, const float* __restrict__ bv) {
    if (blockIdx.z == 0)      gemm_body<1>(g_xh, g_Wqh, bq, g_Qh);
    else if (blockIdx.z == 1) gemm_body<1>(g_xh, g_Wkh, bk, g_Kh);
    else                      gemm_body<2>(g_xh, g_Wvh, bv, g_Vth);
}
__global__ __launch_bounds__(256, 2) void out_gemm_kernel(
    const float* __restrict__ bo, float* __restrict__ out) {
    gemm_body<0>(g_AOh, g_Woh, bo, out);
}

// ---------------- attention v11b (R15, proven): one-chunk skew ------------------
// 4 warps x 32 q-rows, 128-q tiles. smem: Q 16K @0, K[2] 8K @16384/24576,
// V[2] 8K @32768/40960, P[2] 16K @49152/65536 = 80K. 2 CTAs/SM.
#define QSB 0
#define KSB(s) (16384 + (s) * 8192)
#define VSB(s) (32768 + (s) * 8192)
#define PSB(s) (49152 + (s) * 16384)
#define ATTN_SMEM 81920

__global__ __launch_bounds__(128, 2) void attn_kernel(const float* __restrict__ dbias) {
    extern __shared__ __align__(128) char smc[];
    const uint32_t sb = (uint32_t)__cvta_generic_to_shared(smc);
    const int h = blockIdx.x, q0 = blockIdx.y * 128;
    const int tid = threadIdx.x, warp = tid >> 5, lane = tid & 31;
    const int grp = lane >> 2, four = lane & 3;
    const int mb = warp * 32;

    const int lr = tid >> 3, lj = tid & 7;       // loader: row, chunk

    // prologue loads: G0{Q}, G1{K0}, G2{K1,V0}
#pragma unroll
    for (int i = 0; i < 8; i++) {
        int r = lr + i * 16;
        CP16(swad(sb + QSB, r, lj), g_Qh + (size_t)(q0 + r) * D_MODEL + h * 64 + lj * 8);
    }
    CPC;
#pragma unroll
    for (int i = 0; i < 4; i++) {
        int r = lr + i * 16;
        CP16(swad(sb + KSB(0), r, lj), g_Kh + (size_t)(r) * D_MODEL + h * 64 + lj * 8);
    }
    CPC;
#pragma unroll
    for (int i = 0; i < 4; i++) {
        int r = lr + i * 16;
        CP16(swad(sb + KSB(1), r, lj), g_Kh  + (size_t)(64 + r) * D_MODEL + h * 64 + lj * 8);
        CP16(swad(sb + VSB(0), r, lj), g_Vth + (size_t)(h * 64 + r) * N_SEQ + 0 + lj * 8);
    }
    CPC;
    CPW(1);                                      // Q + K0 ready
    __syncthreads();

    float Of[2][8][4], Or[2][8][4];
#pragma unroll
    for (int mi = 0; mi < 2; mi++)
#pragma unroll
        for (int ni = 0; ni < 8; ni++)
#pragma unroll
            for (int j = 0; j < 4; j++) { Of[mi][ni][j] = 0.f; Or[mi][ni][j] = 0.f; }
    float lsum[2][2] = {{0.f, 0.f}, {0.f, 0.f}};
    float lsP[2][2]  = {{0.f, 0.f}, {0.f, 0.f}};

    const float* brow[2][2];
#pragma unroll
    for (int mi = 0; mi < 2; mi++) {
        brow[mi][0] = dbias + (size_t)(q0 + mb + mi * 16 + grp) * N_SEQ;
        brow[mi][1] = brow[mi][0] + (size_t)8 * N_SEQ;
    }

    const int arow0 = mb + (lane & 15);          // + mi*16 ; A-frag rows (Q and P)
    const int acho  = lane >> 4;
    const int brow0f = ((lane >> 4) << 3) + (lane & 7);  // + p*16 ; B-frag rows (K,V)
    const int bcho  = (lane >> 3) & 1;

#pragma unroll 1
    for (int kc = 0; kc < 32; kc++) {
        const int key0 = kc * 64;
        const int s  = kc & 1;                   // slot for K(kc), P(kc)
        const int sp = s ^ 1;                    // slot for V(kc-1), P(kc-1)

        // block boundary bookkeeping: softmax runs 1 chunk ahead of PV
        if (kc && (kc & 3) == 0) {
#pragma unroll
            for (int mi = 0; mi < 2; mi++) {
                lsP[mi][0] = lsum[mi][0]; lsP[mi][1] = lsum[mi][1];
                lsum[mi][0] = 0.f; lsum[mi][1] = 0.f;
            }
        }

        // ---- QK(kc): sc = Q @ K(kc)^T ----
        float sc[2][8][4];
#pragma unroll
        for (int mi = 0; mi < 2; mi++)
#pragma unroll
            for (int ni = 0; ni < 8; ni++)
#pragma unroll
                for (int j = 0; j < 4; j++) sc[mi][ni][j] = 0.f;
#pragma unroll
        for (int g = 0; g < 4; g++) {
            uint32_t a[2][4], bb[4][4];
#pragma unroll
            for (int mi = 0; mi < 2; mi++)
                ldsm4(a[mi], swad(sb + QSB, arow0 + mi * 16, g * 2 + acho));
#pragma unroll
            for (int p = 0; p < 4; p++)
                ldsm4(bb[p], swad(sb + KSB(s), brow0f + p * 16, g * 2 + bcho));
#pragma unroll
            for (int mi = 0; mi < 2; mi++)
#pragma unroll
                for (int ni = 0; ni < 8; ni++)
                    mma_f16(sc[mi][ni], a[mi], &bb[ni >> 1][(ni & 1) << 1]);
        }

        // ---- mixed block: softmax(kc) -> P[s]  ||  PV(kc-1) from P[sp],V[sp] ----
#pragma unroll
        for (int mi = 0; mi < 2; mi++) {
            const int rA = mb + mi * 16 + grp, rB = rA + 8;
#pragma unroll
            for (int ni = 0; ni < 8; ni++) {
                int c = ni * 8 + (four << 1);
                float2 bA = *(const float2*)(brow[mi][0] + key0 + c);
                float2 bB = *(const float2*)(brow[mi][1] + key0 + c);
                float p0 = __expf(fmaf(sc[mi][ni][0], ATTN_SCALE, -bA.x));
                float p1 = __expf(fmaf(sc[mi][ni][1], ATTN_SCALE, -bA.y));
                float p2 = __expf(fmaf(sc[mi][ni][2], ATTN_SCALE, -bB.x));
                float p3 = __expf(fmaf(sc[mi][ni][3], ATTN_SCALE, -bB.y));
                lsum[mi][0] += p0 + p1; lsum[mi][1] += p2 + p3;
                *(uint32_t*)(smc + PSB(s) + rA * 128 + (((ni) ^ (rA & 7)) << 4) + four * 4) = packh2(p0, p1);
                *(uint32_t*)(smc + PSB(s) + rB * 128 + (((ni) ^ (rB & 7)) << 4) + four * 4) = packh2(p2, p3);
            }
        }
        if (kc > 0) {
#pragma unroll
            for (int g = 0; g < 4; g++) {
                uint32_t a[2][4], bb[4][4];
#pragma unroll
                for (int mi = 0; mi < 2; mi++)
                    ldsm4(a[mi], swad(sb + PSB(sp), arow0 + mi * 16, g * 2 + acho));
#pragma unroll
                for (int p = 0; p < 4; p++)
                    ldsm4(bb[p], swad(sb + VSB(sp), brow0f + p * 16, g * 2 + bcho));
#pragma unroll
                for (int mi = 0; mi < 2; mi++)
#pragma unroll
                    for (int ni = 0; ni < 8; ni++)
                        mma_f16(Or[mi][ni], a[mi], &bb[ni >> 1][(ni & 1) << 1]);
            }
        }
        __syncwarp();                            // P[s] stores visible for next iter

        // boundary for block (kc/4 - 1): Or now holds that block's full PV
        if (kc && (kc & 3) == 0) {
#pragma unroll
            for (int mi = 0; mi < 2; mi++) {
                float L0 = lsP[mi][0], L1 = lsP[mi][1];
                L0 += __shfl_xor_sync(0xffffffffu, L0, 1);
                L0 += __shfl_xor_sync(0xffffffffu, L0, 2);
                L1 += __shfl_xor_sync(0xffffffffu, L1, 1);
                L1 += __shfl_xor_sync(0xffffffffu, L1, 2);
                float i0 = 1.0f / L0, i1 = 1.0f / L1;
#pragma unroll
                for (int ni = 0; ni < 8; ni++) {
                    Of[mi][ni][0] += Or[mi][ni][0] * i0;
                    Of[mi][ni][1] += Or[mi][ni][1] * i0;
                    Of[mi][ni][2] += Or[mi][ni][2] * i1;
                    Of[mi][ni][3] += Or[mi][ni][3] * i1;
                    Or[mi][ni][0] = Or[mi][ni][1] = Or[mi][ni][2] = Or[mi][ni][3] = 0.f;
                }
            }
        }

        // refill: K(kc+2) -> slot s (K(kc) dead), V(kc+1) -> slot sp (V(kc-1) dead)
        __syncthreads();
        if (kc <= 29) {
            const int nk = key0 + 128;
#pragma unroll
            for (int i = 0; i < 4; i++) {
                int r = lr + i * 16;
                CP16(swad(sb + KSB(s), r, lj), g_Kh + (size_t)(nk + r) * D_MODEL + h * 64 + lj * 8);
            }
        }
        if (kc <= 30) {
            const int nv = key0 + 64;
#pragma unroll
            for (int i = 0; i < 4; i++) {
                int r = lr + i * 16;
                CP16(swad(sb + VSB(sp), r, lj), g_Vth + (size_t)(h * 64 + r) * N_SEQ + nv + lj * 8);
            }
        }
        CPC;                                      // (possibly empty group near tail)
        CPW(1);                                   // K(kc+1) + V(kc) complete
        __syncthreads();
    }

    // tail: PV(31) + final block boundary (block 7)
#pragma unroll
    for (int mi = 0; mi < 2; mi++) { lsP[mi][0] = lsum[mi][0]; lsP[mi][1] = lsum[mi][1]; }
#pragma unroll
    for (int g = 0; g < 4; g++) {
        uint32_t a[2][4], bb[4][4];
#pragma unroll
        for (int mi = 0; mi < 2; mi++)
            ldsm4(a[mi], swad(sb + PSB(1), arow0 + mi * 16, g * 2 + acho));
#pragma unroll
        for (int p = 0; p < 4; p++)
            ldsm4(bb[p], swad(sb + VSB(1), brow0f + p * 16, g * 2 + bcho));
#pragma unroll
        for (int mi = 0; mi < 2; mi++)
#pragma unroll
            for (int ni = 0; ni < 8; ni++)
                mma_f16(Or[mi][ni], a[mi], &bb[ni >> 1][(ni & 1) << 1]);
    }
#pragma unroll
    for (int mi = 0; mi < 2; mi++) {
        float L0 = lsP[mi][0], L1 = lsP[mi][1];
        L0 += __shfl_xor_sync(0xffffffffu, L0, 1);
        L0 += __shfl_xor_sync(0xffffffffu, L0, 2);
        L1 += __shfl_xor_sync(0xffffffffu, L1, 1);
        L1 += __shfl_xor_sync(0xffffffffu, L1, 2);
        float i0 = 1.0f / L0, i1 = 1.0f / L1;
#pragma unroll
        for (int ni = 0; ni < 8; ni++) {
            Of[mi][ni][0] += Or[mi][ni][0] * i0;
            Of[mi][ni][1] += Or[mi][ni][1] * i0;
            Of[mi][ni][2] += Or[mi][ni][2] * i1;
            Of[mi][ni][3] += Or[mi][ni][3] * i1;
        }
    }

    const float r8 = 1.0f / (8.0f + 1e-8f);      // exact normalizer: nb = 8
#pragma unroll
    for (int mi = 0; mi < 2; mi++) {
#pragma unroll
        for (int ni = 0; ni < 8; ni++) {
            int c = h * 64 + ni * 8 + (four << 1);
            size_t o0 = (size_t)(q0 + mb + mi * 16 + grp) * D_MODEL + c;
            size_t o1 = o0 + (size_t)8 * D_MODEL;
            *(__half2*)(g_AOh + o0) = __floats2half2_rn(Of[mi][ni][0] * r8, Of[mi][ni][1] * r8);
            *(__half2*)(g_AOh + o1) = __floats2half2_rn(Of[mi][ni][2] * r8, Of[mi][ni][3] * r8);
        }
    }
}

// ---------------- launch ---------------------------------------------------------
extern "C" void kernel_launch(void* const* d_in, const int* in_sizes, int n_in,
                              void* d_out, int out_size) {
    const float* x  = (const float*)d_in[0];
    const float* db = (const float*)d_in[1];
    const float* Wq = (const float*)d_in[2];
    const float* bq = (const float*)d_in[3];
    const float* Wk = (const float*)d_in[4];
    const float* bk = (const float*)d_in[5];
    const float* Wv = (const float*)d_in[6];
    const float* bv = (const float*)d_in[7];
    const float* Wo = (const float*)d_in[8];
    const float* bo = (const float*)d_in[9];
    float* out = (float*)d_out;

    cudaFuncSetAttribute(qkv_gemm_kernel, cudaFuncAttributeMaxDynamicSharedMemorySize, GEMM_SMEM);
    cudaFuncSetAttribute(out_gemm_kernel, cudaFuncAttributeMaxDynamicSharedMemorySize, GEMM_SMEM);
    cudaFuncSetAttribute(attn_kernel,     cudaFuncAttributeMaxDynamicSharedMemorySize, ATTN_SMEM);

    prep_kernel<<<dim3(2048, 5), 256>>>((const float4*)x, (const float4*)Wq,
                                        (const float4*)Wk, (const float4*)Wv,
                                        (const float4*)Wo);
    qkv_gemm_kernel<<<dim3(16, 8, 3), 256, GEMM_SMEM>>>(bq, bk, bv);
    attn_kernel<<<dim3(16, 16), 128, ATTN_SMEM>>>(db);
    out_gemm_kernel<<<dim3(16, 8), 256, GEMM_SMEM>>>(bo, out);
}